// round 1
// baseline (speedup 1.0000x reference)
#include <cuda_runtime.h>
#include <math.h>

// Problem constants
#define Bn 2
#define Cn 256
#define Hn 96
#define Wn 96
#define HW (Hn*Wn)          // 9216
#define DGn 4
#define CGn 64
#define KKn 9

// Output layout (tuple order, each tensor flattened C-order)
#define OUT_LOGITS 0                       // [2,1,96,96]  = 18432
#define OUT_BBOX   18432                   // [2,4,96,96]  = 73728
#define OUT_SHAPE  92160                   // [2,2,96,96]  = 36864
#define OUT_LOC    129024                  // [2,1,96,96]  = 18432

// Scratch (device globals; no dynamic allocation allowed)
__device__ float g_x  [Bn*HW*Cn];      // feature NHWC
__device__ float g_t  [Bn*HW*Cn];      // conv1 output NHWC
__device__ float g_off[Bn*HW*72];      // per-pixel offsets, channel order = reference
__device__ float g_w1 [KKn*Cn*Cn];     // conv_w  -> [tap][cin][cout]
__device__ float g_w2 [KKn*Cn*Cn];     // adapt_w -> [(g*9+tap)][ci(64)][cout]

// ---------------------------------------------------------------------------
// Kernel 1: NCHW -> NHWC transpose of feature
// ---------------------------------------------------------------------------
__global__ void k_transpose_feat(const float* __restrict__ x) {
    __shared__ float tile[32][33];
    int b  = blockIdx.z;
    int p0 = blockIdx.x * 32;   // pixel block
    int c0 = blockIdx.y * 32;   // channel block
    int txi = threadIdx.x, tyi = threadIdx.y;  // 32 x 8
    #pragma unroll
    for (int s = 0; s < 32; s += 8)
        tile[tyi + s][txi] = x[(size_t)(b*Cn + c0 + tyi + s)*HW + p0 + txi];
    __syncthreads();
    #pragma unroll
    for (int s = 0; s < 32; s += 8)
        g_x[(size_t)(b*HW + p0 + tyi + s)*Cn + c0 + txi] = tile[txi][tyi + s];
}

// ---------------------------------------------------------------------------
// Kernel 2: weight re-layout
//   g_w1[(tap*256 + c)*256 + o]            = conv_w [(o*256 + c)*9 + tap]
//   g_w2[((g*9+tap)*64 + ci)*256 + o]      = adapt_w[(o*256 + g*64 + ci)*9 + tap]
// ---------------------------------------------------------------------------
__global__ void k_prep_w(const float* __restrict__ conv_w,
                         const float* __restrict__ adapt_w) {
    const int n = KKn*Cn*Cn;  // 589824
    int idx = blockIdx.x * blockDim.x + threadIdx.x;
    if (idx < n) {
        int o   = idx & 255;
        int c   = (idx >> 8) & 255;
        int tap = idx >> 16;
        g_w1[idx] = conv_w[(o*Cn + c)*KKn + tap];
    } else if (idx < 2*n) {
        int j   = idx - n;
        int o   = j & 255;
        int row = j >> 8;          // (g*9+tap)*64 + ci
        int ci  = row & 63;
        int gt  = row >> 6;
        int g   = gt / 9, tap = gt % 9;
        g_w2[j] = adapt_w[(o*Cn + g*CGn + ci)*KKn + tap];
    }
}

// ---------------------------------------------------------------------------
// Kernel 3: conv3x3 (implicit GEMM) + bias + relu  -> g_t (NHWC)
//           fused: loc, shape_pred -> out;  offset -> g_off
// Tile: 64 pixels (4 rows x 16 cols) x 256 out-channels, k-chunk 16, 256 thr.
// ---------------------------------------------------------------------------
__global__ void __launch_bounds__(256, 2)
k_conv1(const float* __restrict__ conv_b_,
        const float* __restrict__ loc_w,  const float* __restrict__ loc_b,
        const float* __restrict__ shape_w,const float* __restrict__ shape_b,
        const float* __restrict__ offset_w,
        float* __restrict__ out) {
    __shared__ float As[16][64];
    __shared__ float Bs[16][256];
    __shared__ float sh_s[64][2];

    const int b  = blockIdx.z;
    const int x0 = blockIdx.x * 16;
    const int y0 = blockIdx.y * 4;
    const int tid = threadIdx.x;
    const int tx = tid & 15;       // out-channel sub-tile
    const int ty = tid >> 4;       // pixel group (4 px each)

    // A-load mapping: 64 px x 16 c, float4 over c
    const int pL  = tid & 63;
    const int c4  = (tid >> 6) * 4;
    const int rL  = pL >> 4, clL = pL & 15;
    // B-load mapping
    const int oB  = (tid & 63) * 4;
    const int cB  = tid >> 6;

    float acc[4][16];
    #pragma unroll
    for (int i = 0; i < 4; ++i)
        #pragma unroll
        for (int j = 0; j < 16; ++j) acc[i][j] = 0.f;

    for (int kt = 0; kt < 144; ++kt) {
        const int tap = kt >> 4;
        const int cc  = (kt & 15) << 4;
        const int dy  = tap / 3 - 1, dx = tap % 3 - 1;

        // stage global loads in registers (overlaps previous GEMM)
        const int yy = y0 + rL + dy, xx = x0 + clL + dx;
        float4 a4 = make_float4(0.f, 0.f, 0.f, 0.f);
        if (yy >= 0 && yy < Hn && xx >= 0 && xx < Wn)
            a4 = *(const float4*)&g_x[((size_t)(b*Hn + yy)*Wn + xx)*Cn + cc + c4];
        float4 b4[4];
        #pragma unroll
        for (int r = 0; r < 4; ++r)
            b4[r] = *(const float4*)&g_w1[(size_t)(tap*Cn + cc + cB + r*4)*Cn + oB];

        __syncthreads();
        As[c4+0][pL] = a4.x; As[c4+1][pL] = a4.y;
        As[c4+2][pL] = a4.z; As[c4+3][pL] = a4.w;
        #pragma unroll
        for (int r = 0; r < 4; ++r)
            *(float4*)&Bs[cB + r*4][oB] = b4[r];
        __syncthreads();

        #pragma unroll
        for (int kk = 0; kk < 16; ++kk) {
            float4 a = *(const float4*)&As[kk][ty*4];
            float av[4] = {a.x, a.y, a.z, a.w};
            #pragma unroll
            for (int q = 0; q < 4; ++q) {
                float4 bb = *(const float4*)&Bs[kk][q*64 + tx*4];
                float bv[4] = {bb.x, bb.y, bb.z, bb.w};
                #pragma unroll
                for (int i = 0; i < 4; ++i)
                    #pragma unroll
                    for (int j = 0; j < 4; ++j)
                        acc[i][q*4+j] += av[i] * bv[j];
            }
        }
    }

    // bias + relu + partial dots for loc/shape
    float pl[4] = {0,0,0,0}, ps0[4] = {0,0,0,0}, ps1[4] = {0,0,0,0};
    #pragma unroll
    for (int q = 0; q < 4; ++q)
        #pragma unroll
        for (int j = 0; j < 4; ++j) {
            const int o = q*64 + tx*4 + j;
            const float cb = conv_b_[o];
            const float lw = loc_w[o];
            const float s0 = shape_w[o];
            const float s1 = shape_w[Cn + o];
            #pragma unroll
            for (int i = 0; i < 4; ++i) {
                float v = fmaxf(acc[i][q*4+j] + cb, 0.f);
                acc[i][q*4+j] = v;
                pl[i]  += v * lw;
                ps0[i] += v * s0;
                ps1[i] += v * s1;
            }
        }

    // write t (NHWC)
    #pragma unroll
    for (int i = 0; i < 4; ++i) {
        const int p = ty*4 + i;
        const int y = y0 + (p >> 4), xg = x0 + (p & 15);
        float* base = &g_t[((size_t)(b*Hn + y)*Wn + xg)*Cn];
        #pragma unroll
        for (int q = 0; q < 4; ++q) {
            float4 v = make_float4(acc[i][q*4+0], acc[i][q*4+1],
                                   acc[i][q*4+2], acc[i][q*4+3]);
            *(float4*)&base[q*64 + tx*4] = v;
        }
    }

    // cross-tx reduction (16 lanes per pixel group) via butterfly shuffles
    #pragma unroll
    for (int i = 0; i < 4; ++i)
        #pragma unroll
        for (int off = 8; off > 0; off >>= 1) {
            pl[i]  += __shfl_xor_sync(0xffffffffu, pl[i],  off);
            ps0[i] += __shfl_xor_sync(0xffffffffu, ps0[i], off);
            ps1[i] += __shfl_xor_sync(0xffffffffu, ps1[i], off);
        }

    if (tx == 0) {
        const float lb = loc_b[0], sb0 = shape_b[0], sb1 = shape_b[1];
        #pragma unroll
        for (int i = 0; i < 4; ++i) {
            const int p = ty*4 + i;
            const int y = y0 + (p >> 4), xg = x0 + (p & 15);
            const int pix = y*Wn + xg;
            out[OUT_LOC   + b*HW + pix]            = pl[i]  + lb;
            const float s0v = ps0[i] + sb0;
            const float s1v = ps1[i] + sb1;
            out[OUT_SHAPE + (b*2 + 0)*HW + pix]    = s0v;
            out[OUT_SHAPE + (b*2 + 1)*HW + pix]    = s1v;
            sh_s[p][0] = s0v;
            sh_s[p][1] = s1v;
        }
    }
    __syncthreads();

    // offsets: 64 px x 72 ch
    for (int idx = tid; idx < 64*72; idx += 256) {
        const int p = idx / 72, j = idx % 72;
        const int y = y0 + (p >> 4), xg = x0 + (p & 15);
        float v = sh_s[p][0] * offset_w[j*2] + sh_s[p][1] * offset_w[j*2 + 1];
        g_off[((size_t)(b*Hn + y)*Wn + xg)*72 + j] = v;
    }
}

// ---------------------------------------------------------------------------
// Kernel 4: deformable conv (implicit GEMM w/ bilinear gather) + relu
//           fused: cls logits + bbox_reg -> out  (ta never materialized)
// ---------------------------------------------------------------------------
__global__ void __launch_bounds__(256, 2)
k_deform(const float* __restrict__ cls_w, const float* __restrict__ cls_b,
         const float* __restrict__ bbox_w, const float* __restrict__ bbox_b,
         float* __restrict__ out) {
    __shared__ float As[16][64];
    __shared__ float Bs[16][256];
    __shared__ float sm_w[4][64];
    __shared__ int   sm_a[4][64];

    const int b  = blockIdx.z;
    const int x0 = blockIdx.x * 16;
    const int y0 = blockIdx.y * 4;
    const int tid = threadIdx.x;
    const int tx = tid & 15;
    const int ty = tid >> 4;

    const int pL  = tid & 63;
    const int c4  = (tid >> 6) * 4;
    const int oB  = (tid & 63) * 4;
    const int cB  = tid >> 6;

    float acc[4][16];
    #pragma unroll
    for (int i = 0; i < 4; ++i)
        #pragma unroll
        for (int j = 0; j < 16; ++j) acc[i][j] = 0.f;

    for (int gt = 0; gt < 36; ++gt) {
        const int g = gt / 9, tap = gt % 9;
        const int dy = tap / 3 - 1, dx = tap % 3 - 1;

        __syncthreads();   // prior A-loads finished reading old meta
        if (tid < 64) {
            const int p = tid;
            const int y = y0 + (p >> 4), xg = x0 + (p & 15);
            const int pixbase = (b*Hn + y)*Wn + xg;
            const float offy = g_off[(size_t)pixbase*72 + g*18 + tap*2 + 0];
            const float offx = g_off[(size_t)pixbase*72 + g*18 + tap*2 + 1];
            const float py  = (float)(y  + dy) + offy;
            const float pxf = (float)(xg + dx) + offx;
            const float y0f = floorf(py), x0f = floorf(pxf);
            const float wy = py - y0f, wx = pxf - x0f;
            const int yi = (int)y0f, xi = (int)x0f;
            const int ys[2] = {yi, yi + 1};
            const int xs[2] = {xi, xi + 1};
            const float wys[2] = {1.f - wy, wy};
            const float wxs[2] = {1.f - wx, wx};
            #pragma unroll
            for (int cy = 0; cy < 2; ++cy)
                #pragma unroll
                for (int cx = 0; cx < 2; ++cx) {
                    const int k = cy*2 + cx;
                    const int yc = ys[cy], xc = xs[cx];
                    const bool valid = (yc >= 0 && yc < Hn && xc >= 0 && xc < Wn);
                    const int ycc = min(max(yc, 0), Hn - 1);
                    const int xcc = min(max(xc, 0), Wn - 1);
                    sm_w[k][p] = valid ? (wys[cy] * wxs[cx]) : 0.f;
                    sm_a[k][p] = ((b*Hn + ycc)*Wn + xcc)*Cn + g*CGn;
                }
        }
        __syncthreads();

        for (int cc4 = 0; cc4 < 4; ++cc4) {
            const int cb = cc4*16 + c4;
            // bilinear-gathered A tile (register staged)
            float w0 = sm_w[0][pL], w1 = sm_w[1][pL];
            float w2 = sm_w[2][pL], w3 = sm_w[3][pL];
            const float4 v0 = *(const float4*)&g_t[(size_t)sm_a[0][pL] + cb];
            const float4 v1 = *(const float4*)&g_t[(size_t)sm_a[1][pL] + cb];
            const float4 v2 = *(const float4*)&g_t[(size_t)sm_a[2][pL] + cb];
            const float4 v3 = *(const float4*)&g_t[(size_t)sm_a[3][pL] + cb];
            float4 a4;
            a4.x = w0*v0.x + w1*v1.x + w2*v2.x + w3*v3.x;
            a4.y = w0*v0.y + w1*v1.y + w2*v2.y + w3*v3.y;
            a4.z = w0*v0.z + w1*v1.z + w2*v2.z + w3*v3.z;
            a4.w = w0*v0.w + w1*v1.w + w2*v2.w + w3*v3.w;
            float4 b4[4];
            #pragma unroll
            for (int r = 0; r < 4; ++r)
                b4[r] = *(const float4*)
                    &g_w2[(size_t)((g*9 + tap)*CGn + cc4*16 + cB + r*4)*Cn + oB];

            __syncthreads();
            As[c4+0][pL] = a4.x; As[c4+1][pL] = a4.y;
            As[c4+2][pL] = a4.z; As[c4+3][pL] = a4.w;
            #pragma unroll
            for (int r = 0; r < 4; ++r)
                *(float4*)&Bs[cB + r*4][oB] = b4[r];
            __syncthreads();

            #pragma unroll
            for (int kk = 0; kk < 16; ++kk) {
                float4 a = *(const float4*)&As[kk][ty*4];
                float av[4] = {a.x, a.y, a.z, a.w};
                #pragma unroll
                for (int q = 0; q < 4; ++q) {
                    float4 bb = *(const float4*)&Bs[kk][q*64 + tx*4];
                    float bv[4] = {bb.x, bb.y, bb.z, bb.w};
                    #pragma unroll
                    for (int i = 0; i < 4; ++i)
                        #pragma unroll
                        for (int j = 0; j < 4; ++j)
                            acc[i][q*4+j] += av[i] * bv[j];
                }
            }
        }
    }

    // relu + cls/bbox partial dots
    float pc[4]    = {0,0,0,0};
    float pb[4][4] = {{0,0,0,0},{0,0,0,0},{0,0,0,0},{0,0,0,0}};
    #pragma unroll
    for (int q = 0; q < 4; ++q)
        #pragma unroll
        for (int j = 0; j < 4; ++j) {
            const int o = q*64 + tx*4 + j;
            const float cw  = cls_w[o];
            const float bw0 = bbox_w[o];
            const float bw1 = bbox_w[Cn + o];
            const float bw2 = bbox_w[2*Cn + o];
            const float bw3 = bbox_w[3*Cn + o];
            #pragma unroll
            for (int i = 0; i < 4; ++i) {
                const float v = fmaxf(acc[i][q*4+j], 0.f);
                pc[i]    += v * cw;
                pb[0][i] += v * bw0;
                pb[1][i] += v * bw1;
                pb[2][i] += v * bw2;
                pb[3][i] += v * bw3;
            }
        }

    #pragma unroll
    for (int i = 0; i < 4; ++i)
        #pragma unroll
        for (int off = 8; off > 0; off >>= 1) {
            pc[i] += __shfl_xor_sync(0xffffffffu, pc[i], off);
            #pragma unroll
            for (int j = 0; j < 4; ++j)
                pb[j][i] += __shfl_xor_sync(0xffffffffu, pb[j][i], off);
        }

    if (tx == 0) {
        const float cb0 = cls_b[0];
        #pragma unroll
        for (int i = 0; i < 4; ++i) {
            const int p = ty*4 + i;
            const int y = y0 + (p >> 4), xg = x0 + (p & 15);
            const int pix = y*Wn + xg;
            out[OUT_LOGITS + b*HW + pix] = pc[i] + cb0;
            #pragma unroll
            for (int j = 0; j < 4; ++j)
                out[OUT_BBOX + (b*4 + j)*HW + pix] = pb[j][i] + bbox_b[j];
        }
    }
}

// ---------------------------------------------------------------------------
extern "C" void kernel_launch(void* const* d_in, const int* in_sizes, int n_in,
                              void* d_out, int out_size) {
    const float* feature  = (const float*)d_in[0];
    const float* conv_w   = (const float*)d_in[1];
    const float* conv_b   = (const float*)d_in[2];
    const float* loc_w    = (const float*)d_in[3];
    const float* loc_b    = (const float*)d_in[4];
    const float* shape_w  = (const float*)d_in[5];
    const float* shape_b  = (const float*)d_in[6];
    const float* offset_w = (const float*)d_in[7];
    const float* adapt_w  = (const float*)d_in[8];
    const float* cls_w    = (const float*)d_in[9];
    const float* cls_b    = (const float*)d_in[10];
    const float* bbox_w   = (const float*)d_in[11];
    const float* bbox_b   = (const float*)d_in[12];
    float* out = (float*)d_out;

    k_transpose_feat<<<dim3(HW/32, Cn/32, Bn), dim3(32, 8)>>>(feature);
    k_prep_w<<<(2*KKn*Cn*Cn + 255)/256, 256>>>(conv_w, adapt_w);
    k_conv1<<<dim3(Wn/16, Hn/4, Bn), 256>>>(conv_b, loc_w, loc_b,
                                            shape_w, shape_b, offset_w, out);
    k_deform<<<dim3(Wn/16, Hn/4, Bn), 256>>>(cls_w, cls_b, bbox_w, bbox_b, out);
}

// round 2
// speedup vs baseline: 1.1497x; 1.1497x over previous
#include <cuda_runtime.h>
#include <math.h>

// Problem constants
#define Bn 2
#define Cn 256
#define Hn 96
#define Wn 96
#define HW (Hn*Wn)          // 9216
#define CGn 64
#define KKn 9

// Output layout (tuple order, each tensor flattened C-order)
#define OUT_LOGITS 0                       // [2,1,96,96]
#define OUT_BBOX   18432                   // [2,4,96,96]
#define OUT_SHAPE  92160                   // [2,2,96,96]
#define OUT_LOC    129024                  // [2,1,96,96]

#define AS_STRIDE 66                       // padded: conflict-free gather stores

typedef unsigned long long u64;

// Scratch (device globals; no dynamic allocation allowed)
__device__ float g_x  [Bn*HW*Cn];      // feature NHWC
__device__ float g_t  [Bn*HW*Cn];      // conv1 output NHWC
__device__ float g_off[Bn*HW*72];      // per-pixel offsets
__device__ float g_w1 [KKn*Cn*Cn];     // conv_w  -> [tap][cin][cout]
__device__ float g_w2 [KKn*Cn*Cn];     // adapt_w -> [(g*9+tap)][ci(64)][cout]

// ---- packed fp32x2 helpers -------------------------------------------------
__device__ __forceinline__ u64 pk2(float lo, float hi) {
    u64 r; asm("mov.b64 %0, {%1,%2};" : "=l"(r) : "f"(lo), "f"(hi)); return r;
}
__device__ __forceinline__ void up2(u64 v, float& lo, float& hi) {
    asm("mov.b64 {%0,%1}, %2;" : "=f"(lo), "=f"(hi) : "l"(v));
}
__device__ __forceinline__ void fma2(u64& d, u64 a, u64 b) {
    asm("fma.rn.f32x2 %0, %1, %2, %0;" : "+l"(d) : "l"(a), "l"(b));
}

// ---------------------------------------------------------------------------
// Kernel 1: NCHW -> NHWC transpose of feature
// ---------------------------------------------------------------------------
__global__ void k_transpose_feat(const float* __restrict__ x) {
    __shared__ float tile[32][33];
    int b  = blockIdx.z;
    int p0 = blockIdx.x * 32;
    int c0 = blockIdx.y * 32;
    int txi = threadIdx.x, tyi = threadIdx.y;  // 32 x 8
    #pragma unroll
    for (int s = 0; s < 32; s += 8)
        tile[tyi + s][txi] = x[(size_t)(b*Cn + c0 + tyi + s)*HW + p0 + txi];
    __syncthreads();
    #pragma unroll
    for (int s = 0; s < 32; s += 8)
        g_x[(size_t)(b*HW + p0 + tyi + s)*Cn + c0 + txi] = tile[txi][tyi + s];
}

// ---------------------------------------------------------------------------
// Kernel 2: weight re-layout
// ---------------------------------------------------------------------------
__global__ void k_prep_w(const float* __restrict__ conv_w,
                         const float* __restrict__ adapt_w) {
    const int n = KKn*Cn*Cn;
    int idx = blockIdx.x * blockDim.x + threadIdx.x;
    if (idx < n) {
        int o   = idx & 255;
        int c   = (idx >> 8) & 255;
        int tap = idx >> 16;
        g_w1[idx] = conv_w[(o*Cn + c)*KKn + tap];
    } else if (idx < 2*n) {
        int j   = idx - n;
        int o   = j & 255;
        int row = j >> 8;
        int ci  = row & 63;
        int gt  = row >> 6;
        int g   = gt / 9, tap = gt % 9;
        g_w2[j] = adapt_w[(o*Cn + g*CGn + ci)*KKn + tap];
    }
}

// ---------------------------------------------------------------------------
// Kernel 3: conv3x3 implicit GEMM (f32x2, double buffered) + fused heads
// Tile: 64 px (4x16) x 256 oc, k-chunk 16, 256 thr, micro 8px x 8oc.
// ---------------------------------------------------------------------------
__global__ void __launch_bounds__(256, 2)
k_conv1(const float* __restrict__ conv_b_,
        const float* __restrict__ loc_w,  const float* __restrict__ loc_b,
        const float* __restrict__ shape_w,const float* __restrict__ shape_b,
        const float* __restrict__ offset_w,
        float* __restrict__ out) {
    __shared__ float As[2][16*AS_STRIDE];
    __shared__ float Bs[2][16*256];
    __shared__ float sh_s[64][2];

    const int b  = blockIdx.z;
    const int x0 = blockIdx.x * 16;
    const int y0 = blockIdx.y * 4;
    const int tid = threadIdx.x;
    const int tx = tid & 31;       // 8 oc each -> 256
    const int ty = tid >> 5;       // 8 px each -> 64

    // A gather mapping: pixel = tid>>2 (64), lane = tid&3 (16ch/4)
    const int pA = tid >> 2, laneA = tid & 3;
    const int rowA = pA >> 4, colA = pA & 15;
    // B load mapping
    const int oB = (tid & 63) * 4, cB = tid >> 6;

    u64 acc[4][8];
    #pragma unroll
    for (int i = 0; i < 4; ++i)
        #pragma unroll
        for (int j = 0; j < 8; ++j) acc[i][j] = 0ull;

    float4 a4; float4 b4[4];

    // prologue: chunk 0 -> buffer 0
    {
        const int yy = y0 + rowA - 1, xx = x0 + colA - 1;
        a4 = make_float4(0.f, 0.f, 0.f, 0.f);
        if (yy >= 0 && yy < Hn && xx >= 0 && xx < Wn)
            a4 = *(const float4*)&g_x[((size_t)((b*Hn + yy)*Wn + xx))*Cn + laneA*4];
        #pragma unroll
        for (int q = 0; q < 4; ++q)
            b4[q] = *(const float4*)&g_w1[(size_t)(cB + q*4)*Cn + oB];
        As[0][(laneA*4+0)*AS_STRIDE + pA] = a4.x;
        As[0][(laneA*4+1)*AS_STRIDE + pA] = a4.y;
        As[0][(laneA*4+2)*AS_STRIDE + pA] = a4.z;
        As[0][(laneA*4+3)*AS_STRIDE + pA] = a4.w;
        #pragma unroll
        for (int q = 0; q < 4; ++q)
            *(float4*)&Bs[0][(cB + q*4)*256 + oB] = b4[q];
    }
    __syncthreads();

    for (int kt = 0; kt < 144; ++kt) {
        const int buf = kt & 1;
        if (kt < 143) {
            const int n   = kt + 1;
            const int tap = n >> 4, cc = (n & 15) << 4;
            const int dy  = tap/3 - 1, dx = tap%3 - 1;
            const int yy = y0 + rowA + dy, xx = x0 + colA + dx;
            a4 = make_float4(0.f, 0.f, 0.f, 0.f);
            if (yy >= 0 && yy < Hn && xx >= 0 && xx < Wn)
                a4 = *(const float4*)&g_x[((size_t)((b*Hn + yy)*Wn + xx))*Cn + cc + laneA*4];
            #pragma unroll
            for (int q = 0; q < 4; ++q)
                b4[q] = *(const float4*)&g_w1[(size_t)(tap*Cn + cc + cB + q*4)*Cn + oB];
        }

        #pragma unroll
        for (int kk = 0; kk < 16; ++kk) {
            const float* ar = &As[buf][kk*AS_STRIDE + ty*8];
            u64 a0 = *(const u64*)(ar + 0);
            u64 a1 = *(const u64*)(ar + 2);
            u64 a2 = *(const u64*)(ar + 4);
            u64 a3 = *(const u64*)(ar + 6);
            const float* br = &Bs[buf][kk*256 + tx*8];
            float4 p0 = *(const float4*)br;
            float4 p1 = *(const float4*)(br + 4);
            u64 bb[8];
            bb[0] = pk2(p0.x, p0.x); bb[1] = pk2(p0.y, p0.y);
            bb[2] = pk2(p0.z, p0.z); bb[3] = pk2(p0.w, p0.w);
            bb[4] = pk2(p1.x, p1.x); bb[5] = pk2(p1.y, p1.y);
            bb[6] = pk2(p1.z, p1.z); bb[7] = pk2(p1.w, p1.w);
            #pragma unroll
            for (int j = 0; j < 8; ++j) {
                fma2(acc[0][j], a0, bb[j]);
                fma2(acc[1][j], a1, bb[j]);
                fma2(acc[2][j], a2, bb[j]);
                fma2(acc[3][j], a3, bb[j]);
            }
        }

        if (kt < 143) {
            const int nb = (kt + 1) & 1;
            As[nb][(laneA*4+0)*AS_STRIDE + pA] = a4.x;
            As[nb][(laneA*4+1)*AS_STRIDE + pA] = a4.y;
            As[nb][(laneA*4+2)*AS_STRIDE + pA] = a4.z;
            As[nb][(laneA*4+3)*AS_STRIDE + pA] = a4.w;
            #pragma unroll
            for (int q = 0; q < 4; ++q)
                *(float4*)&Bs[nb][(cB + q*4)*256 + oB] = b4[q];
        }
        __syncthreads();
    }

    // epilogue: bias + relu, write t, partial dots for loc/shape
    float cbv[8], lwv[8], s0v[8], s1v[8];
    #pragma unroll
    for (int j = 0; j < 8; ++j) {
        const int o = tx*8 + j;
        cbv[j] = conv_b_[o];
        lwv[j] = loc_w[o];
        s0v[j] = shape_w[o];
        s1v[j] = shape_w[Cn + o];
    }

    float pl[8], ps0[8], ps1[8];
    #pragma unroll
    for (int i = 0; i < 8; ++i) { pl[i] = 0.f; ps0[i] = 0.f; ps1[i] = 0.f; }

    #pragma unroll
    for (int i = 0; i < 4; ++i) {
        float vlo[8], vhi[8];
        #pragma unroll
        for (int j = 0; j < 8; ++j) {
            float a, bv; up2(acc[i][j], a, bv);
            vlo[j] = fmaxf(a  + cbv[j], 0.f);
            vhi[j] = fmaxf(bv + cbv[j], 0.f);
            pl[2*i]    += vlo[j]*lwv[j];  pl[2*i+1]  += vhi[j]*lwv[j];
            ps0[2*i]   += vlo[j]*s0v[j];  ps0[2*i+1] += vhi[j]*s0v[j];
            ps1[2*i]   += vlo[j]*s1v[j];  ps1[2*i+1] += vhi[j]*s1v[j];
        }
        const int plo = ty*8 + 2*i;
        float* blo = &g_t[((size_t)((b*Hn + y0 + (plo>>4))*Wn + x0 + (plo&15)))*Cn + tx*8];
        *(float4*)blo     = make_float4(vlo[0], vlo[1], vlo[2], vlo[3]);
        *(float4*)(blo+4) = make_float4(vlo[4], vlo[5], vlo[6], vlo[7]);
        const int phi = plo + 1;
        float* bhi = &g_t[((size_t)((b*Hn + y0 + (phi>>4))*Wn + x0 + (phi&15)))*Cn + tx*8];
        *(float4*)bhi     = make_float4(vhi[0], vhi[1], vhi[2], vhi[3]);
        *(float4*)(bhi+4) = make_float4(vhi[4], vhi[5], vhi[6], vhi[7]);
    }

    // full-warp reduction over tx (32 lanes = full 256 oc)
    #pragma unroll
    for (int i = 0; i < 8; ++i)
        #pragma unroll
        for (int off = 16; off > 0; off >>= 1) {
            pl[i]  += __shfl_xor_sync(0xffffffffu, pl[i],  off);
            ps0[i] += __shfl_xor_sync(0xffffffffu, ps0[i], off);
            ps1[i] += __shfl_xor_sync(0xffffffffu, ps1[i], off);
        }

    if (tx == 0) {
        const float lb = loc_b[0], sb0 = shape_b[0], sb1 = shape_b[1];
        #pragma unroll
        for (int i = 0; i < 8; ++i) {
            const int p = ty*8 + i;
            const int y = y0 + (p >> 4), xg = x0 + (p & 15);
            const int pix = y*Wn + xg;
            out[OUT_LOC + b*HW + pix] = pl[i] + lb;
            const float a0 = ps0[i] + sb0;
            const float a1 = ps1[i] + sb1;
            out[OUT_SHAPE + (b*2 + 0)*HW + pix] = a0;
            out[OUT_SHAPE + (b*2 + 1)*HW + pix] = a1;
            sh_s[p][0] = a0;
            sh_s[p][1] = a1;
        }
    }
    __syncthreads();

    // offsets: 64 px x 72 ch
    for (int idx = tid; idx < 64*72; idx += 256) {
        const int p = idx / 72, j = idx % 72;
        const int y = y0 + (p >> 4), xg = x0 + (p & 15);
        float v = sh_s[p][0] * offset_w[j*2] + sh_s[p][1] * offset_w[j*2 + 1];
        g_off[((size_t)((b*Hn + y)*Wn + xg))*72 + j] = v;
    }
}

// ---------------------------------------------------------------------------
// Kernel 4: deformable conv implicit GEMM (f32x2, double buffered, coalesced
//           bilinear gather) + relu + fused cls/bbox heads
// ---------------------------------------------------------------------------
__global__ void __launch_bounds__(256, 2)
k_deform(const float* __restrict__ cls_w, const float* __restrict__ cls_b,
         const float* __restrict__ bbox_w, const float* __restrict__ bbox_b,
         float* __restrict__ out) {
    __shared__ float As[2][16*AS_STRIDE];
    __shared__ float Bs[2][16*256];

    const int b  = blockIdx.z;
    const int x0 = blockIdx.x * 16;
    const int y0 = blockIdx.y * 4;
    const int tid = threadIdx.x;
    const int tx = tid & 31;
    const int ty = tid >> 5;

    const int pA = tid >> 2, laneA = tid & 3;
    const int yP = y0 + (pA >> 4), xP = x0 + (pA & 15);
    const int pixbase = (b*Hn + yP)*Wn + xP;
    const int oB = (tid & 63) * 4, cB = tid >> 6;

    u64 acc[4][8];
    #pragma unroll
    for (int i = 0; i < 4; ++i)
        #pragma unroll
        for (int j = 0; j < 8; ++j) acc[i][j] = 0ull;

    int   ga[4];
    float gw[4];
    float4 a4; float4 b4[4];

    // bilinear metadata for (group,tap) = gt, computed per-thread in registers
    auto calc_meta = [&](int gt) {
        const int g = gt / 9, tap = gt - g*9;
        const int dy = tap/3 - 1, dx = tap%3 - 1;
        const float offy = g_off[(size_t)pixbase*72 + gt*2 + 0];
        const float offx = g_off[(size_t)pixbase*72 + gt*2 + 1];
        const float py  = (float)(yP + dy) + offy;
        const float pxf = (float)(xP + dx) + offx;
        const float y0f = floorf(py), x0f = floorf(pxf);
        const float wy = py - y0f, wx = pxf - x0f;
        const int yi = (int)y0f, xi = (int)x0f;
        #pragma unroll
        for (int cy = 0; cy < 2; ++cy)
            #pragma unroll
            for (int cx = 0; cx < 2; ++cx) {
                const int k = cy*2 + cx;
                const int yc = yi + cy, xc = xi + cx;
                const bool valid = (yc >= 0 && yc < Hn && xc >= 0 && xc < Wn);
                const int ycc = min(max(yc, 0), Hn - 1);
                const int xcc = min(max(xc, 0), Wn - 1);
                const float wv = (cy ? wy : 1.f - wy) * (cx ? wx : 1.f - wx);
                gw[k] = valid ? wv : 0.f;
                ga[k] = ((b*Hn + ycc)*Wn + xcc)*Cn + g*CGn;
            }
    };

    auto fetch = [&](int n) {     // chunk n: gt = n>>2, cin sub-chunk = n&3
        if ((n & 3) == 0) calc_meta(n >> 2);
        const int cc = (n & 3)*16 + laneA*4;
        const float4 v0 = *(const float4*)&g_t[(size_t)ga[0] + cc];
        const float4 v1 = *(const float4*)&g_t[(size_t)ga[1] + cc];
        const float4 v2 = *(const float4*)&g_t[(size_t)ga[2] + cc];
        const float4 v3 = *(const float4*)&g_t[(size_t)ga[3] + cc];
        a4.x = gw[0]*v0.x + gw[1]*v1.x + gw[2]*v2.x + gw[3]*v3.x;
        a4.y = gw[0]*v0.y + gw[1]*v1.y + gw[2]*v2.y + gw[3]*v3.y;
        a4.z = gw[0]*v0.z + gw[1]*v1.z + gw[2]*v2.z + gw[3]*v3.z;
        a4.w = gw[0]*v0.w + gw[1]*v1.w + gw[2]*v2.w + gw[3]*v3.w;
        #pragma unroll
        for (int q = 0; q < 4; ++q)
            b4[q] = *(const float4*)
                &g_w2[(size_t)((n>>2)*64 + (n&3)*16 + cB + q*4)*Cn + oB];
    };

    auto stage = [&](int nb) {
        As[nb][(laneA*4+0)*AS_STRIDE + pA] = a4.x;
        As[nb][(laneA*4+1)*AS_STRIDE + pA] = a4.y;
        As[nb][(laneA*4+2)*AS_STRIDE + pA] = a4.z;
        As[nb][(laneA*4+3)*AS_STRIDE + pA] = a4.w;
        #pragma unroll
        for (int q = 0; q < 4; ++q)
            *(float4*)&Bs[nb][(cB + q*4)*256 + oB] = b4[q];
    };

    fetch(0);
    stage(0);
    __syncthreads();

    for (int kt = 0; kt < 144; ++kt) {
        const int buf = kt & 1;
        if (kt < 143) fetch(kt + 1);

        #pragma unroll
        for (int kk = 0; kk < 16; ++kk) {
            const float* ar = &As[buf][kk*AS_STRIDE + ty*8];
            u64 a0 = *(const u64*)(ar + 0);
            u64 a1 = *(const u64*)(ar + 2);
            u64 a2 = *(const u64*)(ar + 4);
            u64 a3 = *(const u64*)(ar + 6);
            const float* br = &Bs[buf][kk*256 + tx*8];
            float4 p0 = *(const float4*)br;
            float4 p1 = *(const float4*)(br + 4);
            u64 bb[8];
            bb[0] = pk2(p0.x, p0.x); bb[1] = pk2(p0.y, p0.y);
            bb[2] = pk2(p0.z, p0.z); bb[3] = pk2(p0.w, p0.w);
            bb[4] = pk2(p1.x, p1.x); bb[5] = pk2(p1.y, p1.y);
            bb[6] = pk2(p1.z, p1.z); bb[7] = pk2(p1.w, p1.w);
            #pragma unroll
            for (int j = 0; j < 8; ++j) {
                fma2(acc[0][j], a0, bb[j]);
                fma2(acc[1][j], a1, bb[j]);
                fma2(acc[2][j], a2, bb[j]);
                fma2(acc[3][j], a3, bb[j]);
            }
        }

        if (kt < 143) stage((kt + 1) & 1);
        __syncthreads();
    }

    // epilogue: relu + cls/bbox partial dots
    float cwv[8], b0v[8], b1v[8], b2v[8], b3v[8];
    #pragma unroll
    for (int j = 0; j < 8; ++j) {
        const int o = tx*8 + j;
        cwv[j] = cls_w[o];
        b0v[j] = bbox_w[o];
        b1v[j] = bbox_w[Cn + o];
        b2v[j] = bbox_w[2*Cn + o];
        b3v[j] = bbox_w[3*Cn + o];
    }

    float pc[8], pb0[8], pb1[8], pb2[8], pb3[8];
    #pragma unroll
    for (int i = 0; i < 8; ++i) { pc[i]=0.f; pb0[i]=0.f; pb1[i]=0.f; pb2[i]=0.f; pb3[i]=0.f; }

    #pragma unroll
    for (int i = 0; i < 4; ++i)
        #pragma unroll
        for (int j = 0; j < 8; ++j) {
            float a, bv; up2(acc[i][j], a, bv);
            const float vlo = fmaxf(a,  0.f);
            const float vhi = fmaxf(bv, 0.f);
            pc[2*i]  += vlo*cwv[j];  pc[2*i+1]  += vhi*cwv[j];
            pb0[2*i] += vlo*b0v[j];  pb0[2*i+1] += vhi*b0v[j];
            pb1[2*i] += vlo*b1v[j];  pb1[2*i+1] += vhi*b1v[j];
            pb2[2*i] += vlo*b2v[j];  pb2[2*i+1] += vhi*b2v[j];
            pb3[2*i] += vlo*b3v[j];  pb3[2*i+1] += vhi*b3v[j];
        }

    #pragma unroll
    for (int i = 0; i < 8; ++i)
        #pragma unroll
        for (int off = 16; off > 0; off >>= 1) {
            pc[i]  += __shfl_xor_sync(0xffffffffu, pc[i],  off);
            pb0[i] += __shfl_xor_sync(0xffffffffu, pb0[i], off);
            pb1[i] += __shfl_xor_sync(0xffffffffu, pb1[i], off);
            pb2[i] += __shfl_xor_sync(0xffffffffu, pb2[i], off);
            pb3[i] += __shfl_xor_sync(0xffffffffu, pb3[i], off);
        }

    if (tx == 0) {
        const float cb0 = cls_b[0];
        const float bb0 = bbox_b[0], bb1 = bbox_b[1], bb2 = bbox_b[2], bb3 = bbox_b[3];
        #pragma unroll
        for (int i = 0; i < 8; ++i) {
            const int p = ty*8 + i;
            const int y = y0 + (p >> 4), xg = x0 + (p & 15);
            const int pix = y*Wn + xg;
            out[OUT_LOGITS + b*HW + pix]          = pc[i]  + cb0;
            out[OUT_BBOX + (b*4 + 0)*HW + pix]    = pb0[i] + bb0;
            out[OUT_BBOX + (b*4 + 1)*HW + pix]    = pb1[i] + bb1;
            out[OUT_BBOX + (b*4 + 2)*HW + pix]    = pb2[i] + bb2;
            out[OUT_BBOX + (b*4 + 3)*HW + pix]    = pb3[i] + bb3;
        }
    }
}

// ---------------------------------------------------------------------------
extern "C" void kernel_launch(void* const* d_in, const int* in_sizes, int n_in,
                              void* d_out, int out_size) {
    const float* feature  = (const float*)d_in[0];
    const float* conv_w   = (const float*)d_in[1];
    const float* conv_b   = (const float*)d_in[2];
    const float* loc_w    = (const float*)d_in[3];
    const float* loc_b    = (const float*)d_in[4];
    const float* shape_w  = (const float*)d_in[5];
    const float* shape_b  = (const float*)d_in[6];
    const float* offset_w = (const float*)d_in[7];
    const float* adapt_w  = (const float*)d_in[8];
    const float* cls_w    = (const float*)d_in[9];
    const float* cls_b    = (const float*)d_in[10];
    const float* bbox_w   = (const float*)d_in[11];
    const float* bbox_b   = (const float*)d_in[12];
    float* out = (float*)d_out;

    k_transpose_feat<<<dim3(HW/32, Cn/32, Bn), dim3(32, 8)>>>(feature);
    k_prep_w<<<(2*KKn*Cn*Cn + 255)/256, 256>>>(conv_w, adapt_w);
    k_conv1<<<dim3(Wn/16, Hn/4, Bn), 256>>>(conv_b, loc_w, loc_b,
                                            shape_w, shape_b, offset_w, out);
    k_deform<<<dim3(Wn/16, Hn/4, Bn), 256>>>(cls_w, cls_b, bbox_w, bbox_b, out);
}